// round 1
// baseline (speedup 1.0000x reference)
#include <cuda_runtime.h>
#include <math.h>
#include <stddef.h>

// ---------------- problem constants ----------------
#define SQv   2048
#define Dv    1024
#define Hv    16
#define DHv   64
#define NCv   4096
#define LTv   16      // tables
#define KHv   8       // hash funcs per table
#define LKv   128     // LT*KH
#define NBv   256     // buckets
#define TPPv  1024
#define SSv   1024    // sample budget
#define PPv   64

// ---------------- device scratch (no allocations allowed) ----------------
__device__ __align__(16) float g_xln   [SQv*Dv];
__device__ __align__(16) float g_q     [SQv*Dv];
__device__ __align__(16) float g_k     [SQv*Dv];
__device__ __align__(16) float g_v     [SQv*Dv];
__device__ __align__(16) float g_ctx   [SQv*Dv];
__device__ __align__(16) float g_attn  [SQv*Dv];
__device__ __align__(16) float g_normed[SQv*Dv];
__device__ __align__(16) float g_projn [LKv*NCv];
__device__ __align__(16) float g_projt [LKv*TPPv];
__device__ __align__(16) float g_tanhpt[TPPv*LKv];
__device__ __align__(16) float g_tanhpns[SSv*LKv];
__device__ __align__(16) float g_w1s   [SSv*Dv];
__device__ __align__(16) float g_w2s   [SSv*Dv];
__device__ __align__(16) float g_b1s   [SSv];
__device__ __align__(16) float g_logits[TPPv*SSv];
__device__ __align__(16) float g_acts  [TPPv*SSv];
__device__ __align__(16) float g_trip  [2*TPPv];
__device__ int g_coden[LTv*NCv];
__device__ int g_codet[LTv*TPPv];
__device__ int g_hist [LTv*NBv];
__device__ int g_score[NCv];
__device__ int g_sids [SSv];

// ---------------- LayerNorm ----------------
__global__ void ln_kernel(const float* __restrict__ x, const float* __restrict__ g,
                          const float* __restrict__ b, float* __restrict__ y)
{
    int row = blockIdx.x;
    const float* xr = x + (size_t)row * Dv;
    __shared__ float red[256];
    int tid = threadIdx.x;
    float s = 0.f, ss = 0.f;
    for (int i = tid; i < Dv; i += 256) { float v = xr[i]; s += v; ss += v * v; }
    red[tid] = s; __syncthreads();
    for (int st = 128; st > 0; st >>= 1) { if (tid < st) red[tid] += red[tid + st]; __syncthreads(); }
    float mean = red[0] / Dv;
    __syncthreads();
    red[tid] = ss; __syncthreads();
    for (int st = 128; st > 0; st >>= 1) { if (tid < st) red[tid] += red[tid + st]; __syncthreads(); }
    float var = red[0] / Dv - mean * mean;
    float inv = rsqrtf(var + 1e-12f);
    float* yr = y + (size_t)row * Dv;
    for (int i = tid; i < Dv; i += 256) yr[i] = (xr[i] - mean) * inv * g[i] + b[i];
}

// ---------------- GEMM NT: C[M,N] = A[M,K] * B[N,K]^T (+bias[n]) (+res[m,n]) --------
template<bool HAS_BIAS, bool HAS_RES>
__global__ void gemm_nt(const float* __restrict__ A, const float* __restrict__ Bm,
                        const float* __restrict__ bias, const float* __restrict__ res,
                        float* __restrict__ C, int M, int N, int Kd)
{
    __shared__ float As[16][64];
    __shared__ float Bs[16][64];
    int tid = threadIdx.x;
    int tx = tid & 15, ty = tid >> 4;
    int m0 = blockIdx.y * 64, n0 = blockIdx.x * 64;
    float acc[4][4] = {};
    for (int k0 = 0; k0 < Kd; k0 += 16) {
        int idx = tid * 4;
        int r = idx >> 4, kk = idx & 15;
        float4 av = *(const float4*)(A  + (size_t)(m0 + r) * Kd + k0 + kk);
        As[kk+0][r] = av.x; As[kk+1][r] = av.y; As[kk+2][r] = av.z; As[kk+3][r] = av.w;
        float4 bv = *(const float4*)(Bm + (size_t)(n0 + r) * Kd + k0 + kk);
        Bs[kk+0][r] = bv.x; Bs[kk+1][r] = bv.y; Bs[kk+2][r] = bv.z; Bs[kk+3][r] = bv.w;
        __syncthreads();
        #pragma unroll
        for (int q = 0; q < 16; q++) {
            float a[4], b[4];
            #pragma unroll
            for (int i = 0; i < 4; i++) a[i] = As[q][ty*4+i];
            #pragma unroll
            for (int j = 0; j < 4; j++) b[j] = Bs[q][tx*4+j];
            #pragma unroll
            for (int i = 0; i < 4; i++)
                #pragma unroll
                for (int j = 0; j < 4; j++)
                    acc[i][j] += a[i] * b[j];
        }
        __syncthreads();
    }
    #pragma unroll
    for (int i = 0; i < 4; i++) {
        int m = m0 + ty*4 + i;
        #pragma unroll
        for (int j = 0; j < 4; j++) {
            int n = n0 + tx*4 + j;
            float v = acc[i][j];
            if (HAS_BIAS) v += bias[n];
            if (HAS_RES)  v += res[(size_t)m * N + n];
            C[(size_t)m * N + n] = v;
        }
    }
}

// ---------------- GEMM NN: C[M,N] = A[M,K] * B[K,N] (+bias[n]) (+res[m,n]) --------
template<bool HAS_BIAS, bool HAS_RES>
__global__ void gemm_nn(const float* __restrict__ A, const float* __restrict__ Bm,
                        const float* __restrict__ bias, const float* __restrict__ res,
                        float* __restrict__ C, int M, int N, int Kd)
{
    __shared__ float As[16][64];
    __shared__ float Bs[16][64];
    int tid = threadIdx.x;
    int tx = tid & 15, ty = tid >> 4;
    int m0 = blockIdx.y * 64, n0 = blockIdx.x * 64;
    float acc[4][4] = {};
    for (int k0 = 0; k0 < Kd; k0 += 16) {
        int idx = tid * 4;
        {
            int r = idx >> 4, kk = idx & 15;
            float4 av = *(const float4*)(A + (size_t)(m0 + r) * Kd + k0 + kk);
            As[kk+0][r] = av.x; As[kk+1][r] = av.y; As[kk+2][r] = av.z; As[kk+3][r] = av.w;
        }
        {
            int c = idx & 63, kk = idx >> 6;
            float4 bv = *(const float4*)(Bm + (size_t)(k0 + kk) * N + n0 + c);
            Bs[kk][c+0] = bv.x; Bs[kk][c+1] = bv.y; Bs[kk][c+2] = bv.z; Bs[kk][c+3] = bv.w;
        }
        __syncthreads();
        #pragma unroll
        for (int q = 0; q < 16; q++) {
            float a[4], b[4];
            #pragma unroll
            for (int i = 0; i < 4; i++) a[i] = As[q][ty*4+i];
            #pragma unroll
            for (int j = 0; j < 4; j++) b[j] = Bs[q][tx*4+j];
            #pragma unroll
            for (int i = 0; i < 4; i++)
                #pragma unroll
                for (int j = 0; j < 4; j++)
                    acc[i][j] += a[i] * b[j];
        }
        __syncthreads();
    }
    #pragma unroll
    for (int i = 0; i < 4; i++) {
        int m = m0 + ty*4 + i;
        #pragma unroll
        for (int j = 0; j < 4; j++) {
            int n = n0 + tx*4 + j;
            float v = acc[i][j];
            if (HAS_BIAS) v += bias[n];
            if (HAS_RES)  v += res[(size_t)m * N + n];
            C[(size_t)m * N + n] = v;
        }
    }
}

// ---------------- Fused attention (online softmax) ----------------
__global__ void attn_kernel(const float* __restrict__ q, const float* __restrict__ k,
                            const float* __restrict__ v, const float* __restrict__ mask,
                            float* __restrict__ ctx)
{
    const int h  = blockIdx.y;
    const int q0 = blockIdx.x * 32;
    __shared__ float Qs[32][64];
    __shared__ float Ks[32][64];
    __shared__ float Vs[32][64];
    __shared__ float Sc[32][32];
    int tid = threadIdx.x;
    int qi = tid >> 3, sub = tid & 7;

    for (int idx = tid; idx < 32 * 64; idx += 256) {
        int r = idx >> 6, c = idx & 63;
        Qs[r][c] = q[(size_t)(q0 + r) * Dv + h * DHv + c];
    }
    float o[8];
    #pragma unroll
    for (int i = 0; i < 8; i++) o[i] = 0.f;
    float mrun = -1e30f, lrun = 0.f;
    __syncthreads();

    for (int kt = 0; kt < SQv / 32; kt++) {
        int k0 = kt * 32;
        for (int idx = tid; idx < 32 * 64; idx += 256) {
            int r = idx >> 6, c = idx & 63;
            Ks[r][c] = k[(size_t)(k0 + r) * Dv + h * DHv + c];
            Vs[r][c] = v[(size_t)(k0 + r) * Dv + h * DHv + c];
        }
        __syncthreads();

        float lm = -1e30f;
        float sreg[4];
        #pragma unroll
        for (int jj = 0; jj < 4; jj++) {
            int j = sub + jj * 8;
            float s = 0.f;
            #pragma unroll
            for (int d = 0; d < 64; d++) s += Qs[qi][d] * Ks[j][d];
            s *= 0.125f;                                   // 1/sqrt(DH)
            s += -1000.0f * (1.0f - mask[k0 + j]);
            sreg[jj] = s;
            lm = fmaxf(lm, s);
        }
        #pragma unroll
        for (int off = 1; off < 8; off <<= 1)
            lm = fmaxf(lm, __shfl_xor_sync(0xffffffffu, lm, off));
        float mnew = fmaxf(mrun, lm);
        float ps = 0.f;
        #pragma unroll
        for (int jj = 0; jj < 4; jj++) {
            float p = expf(sreg[jj] - mnew);
            Sc[qi][sub + jj * 8] = p;
            ps += p;
        }
        #pragma unroll
        for (int off = 1; off < 8; off <<= 1)
            ps += __shfl_xor_sync(0xffffffffu, ps, off);
        float alpha = expf(mrun - mnew);
        lrun = lrun * alpha + ps;
        mrun = mnew;
        #pragma unroll
        for (int i = 0; i < 8; i++) o[i] *= alpha;
        __syncwarp();
        #pragma unroll
        for (int j = 0; j < 32; j++) {
            float p = Sc[qi][j];
            #pragma unroll
            for (int i = 0; i < 8; i++) o[i] += p * Vs[j][sub * 8 + i];
        }
        __syncthreads();
    }
    float inv = 1.f / lrun;
    #pragma unroll
    for (int i = 0; i < 8; i++)
        ctx[(size_t)(q0 + qi) * Dv + h * DHv + sub * 8 + i] = o[i] * inv;
}

// ---------------- SimHash codes ----------------
__global__ void coden_kernel()
{
    int idx = blockIdx.x * 256 + threadIdx.x;          // LT*NC = 65536
    if (idx >= LTv * NCv) return;
    int n = idx & (NCv - 1), l = idx >> 12;
    int code = 0;
    #pragma unroll
    for (int kk = 0; kk < KHv; kk++)
        if (g_projn[(size_t)(l * KHv + kk) * NCv + n] > 0.f) code |= (1 << kk);
    g_coden[l * NCv + n] = code;
}

__global__ void codet_kernel()
{
    int idx = blockIdx.x * 256 + threadIdx.x;          // LT*TPP = 16384
    if (idx >= LTv * TPPv) return;
    int t = idx & (TPPv - 1), l = idx >> 10;
    int code = 0;
    #pragma unroll
    for (int kk = 0; kk < KHv; kk++)
        if (g_projt[(size_t)(l * KHv + kk) * TPPv + t] > 0.f) code |= (1 << kk);
    g_codet[l * TPPv + t] = code;
}

__global__ void tanhpt_kernel()
{
    int idx = blockIdx.x * 256 + threadIdx.x;          // TPP*LK
    if (idx >= TPPv * LKv) return;
    int t = idx >> 7, lk = idx & 127;
    g_tanhpt[idx] = tanhf(g_projt[(size_t)lk * TPPv + t]);
}

// ---------------- histogram + score ----------------
__global__ void hist_zero()
{
    int i = blockIdx.x * 256 + threadIdx.x;
    if (i < LTv * NBv) g_hist[i] = 0;
}
__global__ void hist_build()
{
    int idx = blockIdx.x * 256 + threadIdx.x;          // LT*TPP
    if (idx >= LTv * TPPv) return;
    int t = idx & (TPPv - 1), l = idx >> 10;
    atomicAdd(&g_hist[l * NBv + g_codet[l * TPPv + t]], 1);
}
__global__ void score_kernel()
{
    int n = blockIdx.x * 256 + threadIdx.x;
    if (n >= NCv) return;
    int s = 0;
    #pragma unroll
    for (int l = 0; l < LTv; l++) s += g_hist[l * NBv + g_coden[l * NCv + n]];
    g_score[n] = s;
}

// ---------------- stable top-S selection (matches jax.lax.top_k ties) -----------
__global__ void select_kernel()
{
    __shared__ int ssc[NCv];        // 16KB
    __shared__ int red[1024];
    int tid = threadIdx.x;
    for (int i = tid; i < NCv; i += 1024) ssc[i] = g_score[i];
    __syncthreads();

    // binary search for tau = value of S-th largest element
    int lo = 0, hi = LTv * TPPv + 1;   // cnt_ge(0)=NC>=S ; cnt_ge(hi)=0
    while (lo + 1 < hi) {
        int mid = (lo + hi) >> 1;
        int c = 0;
        for (int i = tid; i < NCv; i += 1024) c += (ssc[i] >= mid);
        red[tid] = c; __syncthreads();
        for (int st = 512; st > 0; st >>= 1) { if (tid < st) red[tid] += red[tid + st]; __syncthreads(); }
        int tot = red[0]; __syncthreads();
        if (tot >= SSv) lo = mid; else hi = mid;
    }
    int tau = lo;
    int c = 0;
    for (int i = tid; i < NCv; i += 1024) c += (ssc[i] > tau);
    red[tid] = c; __syncthreads();
    for (int st = 512; st > 0; st >>= 1) { if (tid < st) red[tid] += red[tid + st]; __syncthreads(); }
    int m = red[0];                 // strictly-greater count
    int need = SSv - m;             // equals taken by ascending index
    __syncthreads();

    // prefix ranks over 4096 elems, 4 per thread; pack (gt<<16)|eq
    int base = tid * 4;
    int gtp[4], eqp[4];
    int lgt = 0, leq = 0;
    #pragma unroll
    for (int j = 0; j < 4; j++) {
        int sc = ssc[base + j];
        gtp[j] = lgt; eqp[j] = leq;
        lgt += (sc > tau); leq += (sc == tau);
    }
    red[tid] = (lgt << 16) | leq; __syncthreads();
    for (int off = 1; off < 1024; off <<= 1) {
        int v = (tid >= off) ? red[tid - off] : 0;
        __syncthreads();
        red[tid] += v;
        __syncthreads();
    }
    int excl = (tid == 0) ? 0 : red[tid - 1];
    int egt = excl >> 16, eeq = excl & 0xffff;
    #pragma unroll
    for (int j = 0; j < 4; j++) {
        int sc = ssc[base + j];
        if (sc > tau)                       g_sids[egt + gtp[j]] = base + j;
        else if (sc == tau && (eeq + eqp[j]) < need) g_sids[m + eeq + eqp[j]] = base + j;
    }
}

// ---------------- gathers ----------------
__global__ void gather_kernel(const float* __restrict__ W1, const float* __restrict__ b1,
                              const float* __restrict__ W2)
{
    int idx = blockIdx.x * 256 + threadIdx.x;          // SS*D
    if (idx >= SSv * Dv) return;
    int s = idx >> 10, dcol = idx & 1023;
    int row = g_sids[s];
    g_w1s[idx] = W1[(size_t)row * Dv + dcol];
    g_w2s[idx] = W2[(size_t)row * Dv + dcol];
    if (dcol == 0) g_b1s[s] = b1[row];
}

__global__ void tanhpns_kernel()
{
    int idx = blockIdx.x * 256 + threadIdx.x;          // SS*LK
    if (idx >= SSv * LKv) return;
    int s = idx >> 7, lk = idx & 127;
    g_tanhpns[idx] = tanhf(g_projn[(size_t)lk * NCv + g_sids[s]]);
}

// ---------------- GELU (exact) ----------------
__global__ void gelu_kernel()
{
    int i = blockIdx.x * 256 + threadIdx.x;
    if (i >= TPPv * SSv) return;
    float x = g_logits[i];
    g_acts[i] = 0.5f * x * (1.f + erff(x * 0.70710678118654752f));
}

// ---------------- triplet loss ----------------
__global__ void triplet_kernel(int chunk)
{
    int t = blockIdx.x;
    int tid = threadIdx.x;                             // 128
    __shared__ float vals[SSv];
    __shared__ float svec[128];
    __shared__ float rv[128];
    __shared__ int   ri[128];
    const float* lrow = g_logits + (size_t)t * SSv;

    float apos = 0.f, aneg = 0.f;
    for (int phase = 0; phase < 2; phase++) {
        for (int i = tid; i < SSv; i += 128) vals[i] = lrow[i];
        svec[tid] = 0.f;
        __syncthreads();
        for (int it = 0; it < PPv; it++) {
            float bm = (phase == 0) ? -1e30f : 1e30f;
            int bi = SSv;
            for (int i = tid; i < SSv; i += 128) {
                float v = vals[i];
                bool better = (phase == 0) ? (v > bm) : (v < bm);
                if (better) { bm = v; bi = i; }
            }
            rv[tid] = bm; ri[tid] = bi; __syncthreads();
            for (int st = 64; st > 0; st >>= 1) {
                if (tid < st) {
                    float ov = rv[tid + st]; int oi = ri[tid + st];
                    bool better = (phase == 0)
                        ? (ov > rv[tid] || (ov == rv[tid] && oi < ri[tid]))
                        : (ov < rv[tid] || (ov == rv[tid] && oi < ri[tid]));
                    if (better) { rv[tid] = ov; ri[tid] = oi; }
                }
                __syncthreads();
            }
            int idx = ri[0];
            svec[tid] += g_tanhpns[(size_t)idx * LKv + tid];
            if (tid == 0) vals[idx] = (phase == 0) ? -1e30f : 1e30f;
            __syncthreads();
        }
        rv[tid] = svec[tid] * g_tanhpt[(size_t)t * LKv + tid];
        __syncthreads();
        for (int st = 64; st > 0; st >>= 1) { if (tid < st) rv[tid] += rv[tid + st]; __syncthreads(); }
        float a = rv[0] * (1.0f / (128.0f * 64.0f));
        if (phase == 0) apos = a; else aneg = a;
        __syncthreads();
    }
    if (tid == 0) g_trip[chunk * TPPv + t] = fmaxf(aneg - apos + 0.5f, 0.f);
}

__global__ void trip_reduce(float* __restrict__ outp)
{
    __shared__ float red[1024];
    int tid = threadIdx.x;
    red[tid] = g_trip[tid] + g_trip[tid + 1024];
    __syncthreads();
    for (int st = 512; st > 0; st >>= 1) { if (tid < st) red[tid] += red[tid + st]; __syncthreads(); }
    if (tid == 0) *outp = red[0] * (1.0f / 2048.0f);
}

// ---------------- host ----------------
extern "C" void kernel_launch(void* const* d_in, const int* in_sizes, int n_in,
                              void* d_out, int out_size)
{
    const float* hidden = (const float*)d_in[0];
    const float* amask  = (const float*)d_in[1];
    const float* ln1_g  = (const float*)d_in[2];
    const float* ln1_b  = (const float*)d_in[3];
    const float* Wq     = (const float*)d_in[4];
    const float* bq     = (const float*)d_in[5];
    const float* Wk     = (const float*)d_in[6];
    const float* bk     = (const float*)d_in[7];
    const float* Wv     = (const float*)d_in[8];
    const float* bv     = (const float*)d_in[9];
    const float* Wo     = (const float*)d_in[10];
    const float* bo     = (const float*)d_in[11];
    const float* ln2_g  = (const float*)d_in[12];
    const float* ln2_b  = (const float*)d_in[13];
    const float* W1     = (const float*)d_in[14];
    const float* b1     = (const float*)d_in[15];
    const float* Whash  = (const float*)d_in[16];
    const float* W2     = (const float*)d_in[17];
    const float* b2     = (const float*)d_in[18];
    float* out = (float*)d_out;

    float *xln, *q, *k, *v, *ctx, *attn, *normed, *projn, *projt;
    float *w1s, *w2s, *b1s, *logits, *acts;
    cudaGetSymbolAddress((void**)&xln,    g_xln);
    cudaGetSymbolAddress((void**)&q,      g_q);
    cudaGetSymbolAddress((void**)&k,      g_k);
    cudaGetSymbolAddress((void**)&v,      g_v);
    cudaGetSymbolAddress((void**)&ctx,    g_ctx);
    cudaGetSymbolAddress((void**)&attn,   g_attn);
    cudaGetSymbolAddress((void**)&normed, g_normed);
    cudaGetSymbolAddress((void**)&projn,  g_projn);
    cudaGetSymbolAddress((void**)&projt,  g_projt);
    cudaGetSymbolAddress((void**)&w1s,    g_w1s);
    cudaGetSymbolAddress((void**)&w2s,    g_w2s);
    cudaGetSymbolAddress((void**)&b1s,    g_b1s);
    cudaGetSymbolAddress((void**)&logits, g_logits);
    cudaGetSymbolAddress((void**)&acts,   g_acts);

    // ---- attention path ----
    ln_kernel<<<SQv, 256>>>(hidden, ln1_g, ln1_b, xln);
    dim3 gqkv(Dv / 64, SQv / 64);
    gemm_nt<true, false><<<gqkv, 256>>>(xln, Wq, bq, nullptr, q, SQv, Dv, Dv);
    gemm_nt<true, false><<<gqkv, 256>>>(xln, Wk, bk, nullptr, k, SQv, Dv, Dv);
    gemm_nt<true, false><<<gqkv, 256>>>(xln, Wv, bv, nullptr, v, SQv, Dv, Dv);
    attn_kernel<<<dim3(SQv / 32, Hv), 256>>>(q, k, v, amask, ctx);
    gemm_nt<true, true><<<gqkv, 256>>>(ctx, Wo, bo, hidden, attn, SQv, Dv, Dv);

    // ---- FFN prep ----
    ln_kernel<<<SQv, 256>>>(attn, ln2_g, ln2_b, normed);
    gemm_nt<false, false><<<dim3(NCv / 64, LKv / 64), 256>>>(Whash, W1, nullptr, nullptr,
                                                             projn, LKv, NCv, Dv);
    coden_kernel<<<(LTv * NCv) / 256, 256>>>();

    // ---- per-chunk LSH FFN ----
    for (int c = 0; c < 2; c++) {
        const float* hch = normed + (size_t)c * TPPv * Dv;
        const float* ach = attn   + (size_t)c * TPPv * Dv;
        float*       och = out    + (size_t)c * TPPv * Dv;

        gemm_nt<false, false><<<dim3(TPPv / 64, LKv / 64), 256>>>(Whash, hch, nullptr, nullptr,
                                                                  projt, LKv, TPPv, Dv);
        codet_kernel<<<(LTv * TPPv) / 256, 256>>>();
        tanhpt_kernel<<<(TPPv * LKv) / 256, 256>>>();
        hist_zero<<<(LTv * NBv) / 256, 256>>>();
        hist_build<<<(LTv * TPPv) / 256, 256>>>();
        score_kernel<<<NCv / 256, 256>>>();
        select_kernel<<<1, 1024>>>();
        gather_kernel<<<(SSv * Dv) / 256, 256>>>(W1, b1, W2);
        tanhpns_kernel<<<(SSv * LKv) / 256, 256>>>();

        gemm_nt<true, false><<<dim3(SSv / 64, TPPv / 64), 256>>>(hch, w1s, b1s, nullptr,
                                                                 logits, TPPv, SSv, Dv);
        triplet_kernel<<<TPPv, 128>>>(c);
        gelu_kernel<<<(TPPv * SSv) / 256, 256>>>();
        gemm_nn<true, true><<<dim3(Dv / 64, TPPv / 64), 256>>>(acts, w2s, b2, ach,
                                                               och, TPPv, Dv, SSv);
    }

    // ---- scalar output ----
    trip_reduce<<<1, 1024>>>(out + (size_t)SQv * Dv);
}

// round 2
// speedup vs baseline: 4.2689x; 4.2689x over previous
#include <cuda_runtime.h>
#include <math.h>
#include <stddef.h>

// ---------------- problem constants ----------------
#define SQv   2048
#define Dv    1024
#define Hv    16
#define DHv   64
#define NCv   4096
#define LTv   16      // tables
#define KHv   8       // hash funcs per table
#define LKv   128     // LT*KH
#define NBv   256     // buckets
#define TPPv  1024
#define SSv   1024    // sample budget
#define PPv   64

// ---------------- device scratch ----------------
__device__ __align__(16) float g_xln   [SQv*Dv];
__device__ __align__(16) float g_q     [SQv*Dv];
__device__ __align__(16) float g_k     [SQv*Dv];
__device__ __align__(16) float g_v     [SQv*Dv];
__device__ __align__(16) float g_ctx   [SQv*Dv];
__device__ __align__(16) float g_attn  [SQv*Dv];
__device__ __align__(16) float g_normed[SQv*Dv];
__device__ __align__(16) float g_projn [LKv*NCv];
__device__ __align__(16) float g_projt [LKv*TPPv];
__device__ __align__(16) float g_tanhpt[TPPv*LKv];
__device__ __align__(16) float g_tanhpns[SSv*LKv];
__device__ __align__(16) float g_w1s   [SSv*Dv];
__device__ __align__(16) float g_w2sT  [Dv*SSv];
__device__ __align__(16) float g_b1s   [SSv];
__device__ __align__(16) float g_logits[TPPv*SSv];
__device__ __align__(16) float g_acts  [TPPv*SSv];
__device__ __align__(16) float g_trip  [2*TPPv];
__device__ int g_coden[LTv*NCv];
__device__ int g_codet[LTv*TPPv];
__device__ int g_hist [LTv*NBv];
__device__ int g_score[NCv];
__device__ int g_sids [SSv];

// ---------------- helpers ----------------
__device__ __forceinline__ unsigned f2tf(float x){
    unsigned u; asm("cvt.rna.tf32.f32 %0, %1;" : "=r"(u) : "f"(x)); return u;
}
__device__ __forceinline__ void mma8(float* d, const unsigned* a, const unsigned* b){
    asm volatile("mma.sync.aligned.m16n8k8.row.col.f32.tf32.tf32.f32 "
        "{%0,%1,%2,%3},{%4,%5,%6,%7},{%8,%9},{%0,%1,%2,%3};"
        : "+f"(d[0]), "+f"(d[1]), "+f"(d[2]), "+f"(d[3])
        : "r"(a[0]), "r"(a[1]), "r"(a[2]), "r"(a[3]), "r"(b[0]), "r"(b[1]));
}
__device__ __forceinline__ float gelu_exact(float x){
    return 0.5f * x * (1.f + erff(x * 0.70710678118654752f));
}

// ---------------- LayerNorm ----------------
__global__ void ln_kernel(const float* __restrict__ x, const float* __restrict__ g,
                          const float* __restrict__ b, float* __restrict__ y)
{
    int row = blockIdx.x;
    const float* xr = x + (size_t)row * Dv;
    __shared__ float red[256];
    int tid = threadIdx.x;
    float s = 0.f, ss = 0.f;
    for (int i = tid; i < Dv; i += 256) { float v = xr[i]; s += v; ss += v * v; }
    red[tid] = s; __syncthreads();
    for (int st = 128; st > 0; st >>= 1) { if (tid < st) red[tid] += red[tid + st]; __syncthreads(); }
    float mean = red[0] / Dv;
    __syncthreads();
    red[tid] = ss; __syncthreads();
    for (int st = 128; st > 0; st >>= 1) { if (tid < st) red[tid] += red[tid + st]; __syncthreads(); }
    float var = red[0] / Dv - mean * mean;
    float inv = rsqrtf(var + 1e-12f);
    float* yr = y + (size_t)row * Dv;
    for (int i = tid; i < Dv; i += 256) yr[i] = (xr[i] - mean) * inv * g[i] + b[i];
}

// ---------------- TF32 tensor-core GEMM NT ----------------
// C[M,N] = A[M,K]*B[N,K]^T ; SPLIT=3 -> 3xTF32 (fp32-class), SPLIT=1 -> plain TF32.
// EPI==1: write C (=logits) and gelu(C) into C2.
template<int SPLIT, int EPI, bool BIAS, bool RES, int BM_, int BN_>
__global__ void __launch_bounds__(256, 1)
mma_nt(const float* __restrict__ A, const float* __restrict__ B,
       const float* __restrict__ bias, const float* __restrict__ res,
       float* __restrict__ C, float* __restrict__ C2, int M, int N, int K)
{
    constexpr int BK = 32, LD = 36;
    constexpr int WARPS_M = 2;
    constexpr int WTM = BM_ / 2, WTN = BN_ / 4;
    constexpr int MT = WTM / 16, NT = WTN / 8;
    extern __shared__ unsigned sm[];
    unsigned* Ah = sm;
    unsigned* Bh = Ah + BM_ * LD;
    unsigned* Al = (SPLIT == 3) ? Bh + BN_ * LD : Ah;
    unsigned* Bl = (SPLIT == 3) ? Al + BM_ * LD : Bh;

    const int tid = threadIdx.x;
    const int lane = tid & 31, wid = tid >> 5;
    const int wm = wid & 1, wn = wid >> 1;
    const int m0 = blockIdx.y * BM_, n0 = blockIdx.x * BN_;

    constexpr int PA = BM_ / 32;
    constexpr int PB = BN_ / 32;
    const int lrw = tid >> 3;
    const int lcc = (tid & 7) * 4;

    float4 pa[PA], pb[PB];
    float acc[MT][NT][4];
    #pragma unroll
    for (int i = 0; i < MT; i++)
        #pragma unroll
        for (int j = 0; j < NT; j++)
            #pragma unroll
            for (int u = 0; u < 4; u++) acc[i][j][u] = 0.f;

    #pragma unroll
    for (int p = 0; p < PA; p++)
        pa[p] = *(const float4*)(A + (size_t)(m0 + p*32 + lrw) * K + lcc);
    #pragma unroll
    for (int p = 0; p < PB; p++)
        pb[p] = *(const float4*)(B + (size_t)(n0 + p*32 + lrw) * K + lcc);

    const int ntiles = K / BK;
    for (int kt = 0; kt < ntiles; kt++) {
        __syncthreads();
        #pragma unroll
        for (int p = 0; p < PA; p++) {
            float vv[4] = {pa[p].x, pa[p].y, pa[p].z, pa[p].w};
            #pragma unroll
            for (int i = 0; i < 4; i++) {
                unsigned h = f2tf(vv[i]);
                Ah[(p*32 + lrw) * LD + lcc + i] = h;
                if (SPLIT == 3)
                    Al[(p*32 + lrw) * LD + lcc + i] = f2tf(vv[i] - __uint_as_float(h));
            }
        }
        #pragma unroll
        for (int p = 0; p < PB; p++) {
            float vv[4] = {pb[p].x, pb[p].y, pb[p].z, pb[p].w};
            #pragma unroll
            for (int i = 0; i < 4; i++) {
                unsigned h = f2tf(vv[i]);
                Bh[(p*32 + lrw) * LD + lcc + i] = h;
                if (SPLIT == 3)
                    Bl[(p*32 + lrw) * LD + lcc + i] = f2tf(vv[i] - __uint_as_float(h));
            }
        }
        __syncthreads();
        if (kt + 1 < ntiles) {
            const float* An = A + (size_t)(kt + 1) * BK;
            const float* Bn = B + (size_t)(kt + 1) * BK;
            #pragma unroll
            for (int p = 0; p < PA; p++)
                pa[p] = *(const float4*)(An + (size_t)(m0 + p*32 + lrw) * K + lcc);
            #pragma unroll
            for (int p = 0; p < PB; p++)
                pb[p] = *(const float4*)(Bn + (size_t)(n0 + p*32 + lrw) * K + lcc);
        }
        #pragma unroll
        for (int ks = 0; ks < 4; ks++) {
            unsigned ah[MT][4], al[MT][4], bh[NT][2], bl[NT][2];
            #pragma unroll
            for (int i = 0; i < MT; i++) {
                int r = wm * WTM + i * 16 + (lane >> 2);
                int c = ks * 8 + (lane & 3);
                ah[i][0] = Ah[r*LD + c];       ah[i][1] = Ah[(r+8)*LD + c];
                ah[i][2] = Ah[r*LD + c + 4];   ah[i][3] = Ah[(r+8)*LD + c + 4];
                if (SPLIT == 3) {
                    al[i][0] = Al[r*LD + c];     al[i][1] = Al[(r+8)*LD + c];
                    al[i][2] = Al[r*LD + c + 4]; al[i][3] = Al[(r+8)*LD + c + 4];
                }
            }
            #pragma unroll
            for (int j = 0; j < NT; j++) {
                int r = wn * WTN + j * 8 + (lane >> 2);
                int c = ks * 8 + (lane & 3);
                bh[j][0] = Bh[r*LD + c];  bh[j][1] = Bh[r*LD + c + 4];
                if (SPLIT == 3) {
                    bl[j][0] = Bl[r*LD + c];  bl[j][1] = Bl[r*LD + c + 4];
                }
            }
            #pragma unroll
            for (int i = 0; i < MT; i++)
                #pragma unroll
                for (int j = 0; j < NT; j++) {
                    mma8(acc[i][j], ah[i], bh[j]);
                    if (SPLIT == 3) {
                        mma8(acc[i][j], ah[i], bl[j]);
                        mma8(acc[i][j], al[i], bh[j]);
                    }
                }
        }
    }
    // epilogue
    #pragma unroll
    for (int i = 0; i < MT; i++) {
        #pragma unroll
        for (int j = 0; j < NT; j++) {
            int r = m0 + wm * WTM + i * 16 + (lane >> 2);
            int c = n0 + wn * WTN + j * 8 + (lane & 3) * 2;
            float v00 = acc[i][j][0], v01 = acc[i][j][1];
            float v10 = acc[i][j][2], v11 = acc[i][j][3];
            if (BIAS) { float b0 = bias[c], b1 = bias[c+1]; v00 += b0; v01 += b1; v10 += b0; v11 += b1; }
            if (RES) {
                v00 += res[(size_t)r*N + c];     v01 += res[(size_t)r*N + c + 1];
                v10 += res[(size_t)(r+8)*N + c]; v11 += res[(size_t)(r+8)*N + c + 1];
            }
            *(float2*)(C + (size_t)r*N + c)     = make_float2(v00, v01);
            *(float2*)(C + (size_t)(r+8)*N + c) = make_float2(v10, v11);
            if (EPI == 1) {
                *(float2*)(C2 + (size_t)r*N + c)     = make_float2(gelu_exact(v00), gelu_exact(v01));
                *(float2*)(C2 + (size_t)(r+8)*N + c) = make_float2(gelu_exact(v10), gelu_exact(v11));
            }
        }
    }
}

// ---------------- exact-fp32 GEMM NT (hash projections only) ----------------
template<bool HAS_BIAS>
__global__ void gemm_nt(const float* __restrict__ A, const float* __restrict__ Bm,
                        const float* __restrict__ bias,
                        float* __restrict__ C, int M, int N, int Kd)
{
    __shared__ float As[16][64];
    __shared__ float Bs[16][64];
    int tid = threadIdx.x;
    int tx = tid & 15, ty = tid >> 4;
    int m0 = blockIdx.y * 64, n0 = blockIdx.x * 64;
    float acc[4][4] = {};
    for (int k0 = 0; k0 < Kd; k0 += 16) {
        int idx = tid * 4;
        int r = idx >> 4, kk = idx & 15;
        float4 av = *(const float4*)(A  + (size_t)(m0 + r) * Kd + k0 + kk);
        As[kk+0][r] = av.x; As[kk+1][r] = av.y; As[kk+2][r] = av.z; As[kk+3][r] = av.w;
        float4 bv = *(const float4*)(Bm + (size_t)(n0 + r) * Kd + k0 + kk);
        Bs[kk+0][r] = bv.x; Bs[kk+1][r] = bv.y; Bs[kk+2][r] = bv.z; Bs[kk+3][r] = bv.w;
        __syncthreads();
        #pragma unroll
        for (int q = 0; q < 16; q++) {
            float a[4], b[4];
            #pragma unroll
            for (int i = 0; i < 4; i++) a[i] = As[q][ty*4+i];
            #pragma unroll
            for (int j = 0; j < 4; j++) b[j] = Bs[q][tx*4+j];
            #pragma unroll
            for (int i = 0; i < 4; i++)
                #pragma unroll
                for (int j = 0; j < 4; j++)
                    acc[i][j] += a[i] * b[j];
        }
        __syncthreads();
    }
    #pragma unroll
    for (int i = 0; i < 4; i++) {
        int m = m0 + ty*4 + i;
        #pragma unroll
        for (int j = 0; j < 4; j++) {
            int n = n0 + tx*4 + j;
            float v = acc[i][j];
            if (HAS_BIAS) v += bias[n];
            C[(size_t)m * N + n] = v;
        }
    }
}

// ---------------- attention (fp32, conflict-free smem) ----------------
__global__ void __launch_bounds__(256, 2)
attn2(const float* __restrict__ q, const float* __restrict__ k,
      const float* __restrict__ v, const float* __restrict__ mask,
      float* __restrict__ ctx)
{
    extern __shared__ float sa[];
    float* Qs = sa;               // 64*65
    float* Ks = Qs + 64*65;
    float* Vs = Ks + 64*65;
    float* Ps = Vs + 64*65;
    float* Ms = Ps + 64*65;       // 64
    const int tid = threadIdx.x;
    const int tx = tid & 15, ty = tid >> 4;
    const int h = blockIdx.y, q0 = blockIdx.x * 64;

    for (int idx = tid; idx < 64*16; idx += 256) {
        int r = idx >> 4, c4 = (idx & 15) * 4;
        float4 t = *(const float4*)(q + (size_t)(q0 + r) * Dv + h * 64 + c4);
        Qs[r*65 + c4] = t.x; Qs[r*65 + c4 + 1] = t.y;
        Qs[r*65 + c4 + 2] = t.z; Qs[r*65 + c4 + 3] = t.w;
    }
    float o[4][4];
    float mr[4], lrn[4];
    #pragma unroll
    for (int i = 0; i < 4; i++) {
        mr[i] = -1e30f; lrn[i] = 0.f;
        #pragma unroll
        for (int j = 0; j < 4; j++) o[i][j] = 0.f;
    }

    for (int kt = 0; kt < SQv/64; kt++) {
        int k0 = kt * 64;
        __syncthreads();
        for (int idx = tid; idx < 64*16; idx += 256) {
            int r = idx >> 4, c4 = (idx & 15) * 4;
            float4 tk = *(const float4*)(k + (size_t)(k0 + r) * Dv + h * 64 + c4);
            Ks[r*65 + c4] = tk.x; Ks[r*65 + c4 + 1] = tk.y;
            Ks[r*65 + c4 + 2] = tk.z; Ks[r*65 + c4 + 3] = tk.w;
            float4 tv = *(const float4*)(v + (size_t)(k0 + r) * Dv + h * 64 + c4);
            Vs[r*65 + c4] = tv.x; Vs[r*65 + c4 + 1] = tv.y;
            Vs[r*65 + c4 + 2] = tv.z; Vs[r*65 + c4 + 3] = tv.w;
        }
        if (tid < 64) Ms[tid] = -1000.f * (1.f - mask[k0 + tid]);
        __syncthreads();

        float s[4][4];
        #pragma unroll
        for (int i = 0; i < 4; i++)
            #pragma unroll
            for (int j = 0; j < 4; j++) s[i][j] = 0.f;
        #pragma unroll
        for (int d = 0; d < 64; d++) {
            float a[4], b[4];
            #pragma unroll
            for (int i = 0; i < 4; i++) a[i] = Qs[(ty + 16*i)*65 + d];
            #pragma unroll
            for (int j = 0; j < 4; j++) b[j] = Ks[(tx + 16*j)*65 + d];
            #pragma unroll
            for (int i = 0; i < 4; i++)
                #pragma unroll
                for (int j = 0; j < 4; j++) s[i][j] += a[i] * b[j];
        }
        float msr[4];
        #pragma unroll
        for (int j = 0; j < 4; j++) msr[j] = Ms[tx + 16*j];
        #pragma unroll
        for (int i = 0; i < 4; i++) {
            float mx = -1e30f;
            #pragma unroll
            for (int j = 0; j < 4; j++) {
                s[i][j] = s[i][j] * 0.125f + msr[j];
                mx = fmaxf(mx, s[i][j]);
            }
            #pragma unroll
            for (int off = 8; off > 0; off >>= 1)
                mx = fmaxf(mx, __shfl_xor_sync(0xffffffffu, mx, off));
            float mnew = fmaxf(mr[i], mx);
            float al = expf(mr[i] - mnew);
            float ps = 0.f;
            #pragma unroll
            for (int j = 0; j < 4; j++) {
                float p = expf(s[i][j] - mnew);
                Ps[(ty + 16*i)*65 + tx + 16*j] = p;
                ps += p;
            }
            #pragma unroll
            for (int off = 8; off > 0; off >>= 1)
                ps += __shfl_xor_sync(0xffffffffu, ps, off);
            lrn[i] = lrn[i] * al + ps;
            mr[i] = mnew;
            #pragma unroll
            for (int j = 0; j < 4; j++) o[i][j] *= al;
        }
        __syncthreads();
        #pragma unroll
        for (int kk = 0; kk < 64; kk++) {
            float a[4], b[4];
            #pragma unroll
            for (int i = 0; i < 4; i++) a[i] = Ps[(ty + 16*i)*65 + kk];
            #pragma unroll
            for (int j = 0; j < 4; j++) b[j] = Vs[kk*65 + tx + 16*j];
            #pragma unroll
            for (int i = 0; i < 4; i++)
                #pragma unroll
                for (int j = 0; j < 4; j++) o[i][j] += a[i] * b[j];
        }
    }
    #pragma unroll
    for (int i = 0; i < 4; i++) {
        float inv = 1.f / lrn[i];
        #pragma unroll
        for (int j = 0; j < 4; j++)
            ctx[(size_t)(q0 + ty + 16*i) * Dv + h * 64 + tx + 16*j] = o[i][j] * inv;
    }
}

// ---------------- SimHash codes ----------------
__global__ void coden_kernel()
{
    int idx = blockIdx.x * 256 + threadIdx.x;
    if (idx >= LTv * NCv) return;
    int n = idx & (NCv - 1), l = idx >> 12;
    int code = 0;
    #pragma unroll
    for (int kk = 0; kk < KHv; kk++)
        if (g_projn[(size_t)(l * KHv + kk) * NCv + n] > 0.f) code |= (1 << kk);
    g_coden[l * NCv + n] = code;
}
__global__ void codet_kernel()
{
    int idx = blockIdx.x * 256 + threadIdx.x;
    if (idx >= LTv * TPPv) return;
    int t = idx & (TPPv - 1), l = idx >> 10;
    int code = 0;
    #pragma unroll
    for (int kk = 0; kk < KHv; kk++)
        if (g_projt[(size_t)(l * KHv + kk) * TPPv + t] > 0.f) code |= (1 << kk);
    g_codet[l * TPPv + t] = code;
}
__global__ void tanhpt_kernel()
{
    int idx = blockIdx.x * 256 + threadIdx.x;
    if (idx >= TPPv * LKv) return;
    int t = idx >> 7, lk = idx & 127;
    g_tanhpt[idx] = tanhf(g_projt[(size_t)lk * TPPv + t]);
}

// ---------------- histogram + score ----------------
__global__ void hist_zero()
{
    int i = blockIdx.x * 256 + threadIdx.x;
    if (i < LTv * NBv) g_hist[i] = 0;
}
__global__ void hist_build()
{
    int idx = blockIdx.x * 256 + threadIdx.x;
    if (idx >= LTv * TPPv) return;
    int t = idx & (TPPv - 1), l = idx >> 10;
    atomicAdd(&g_hist[l * NBv + g_codet[l * TPPv + t]], 1);
}
__global__ void score_kernel()
{
    int n = blockIdx.x * 256 + threadIdx.x;
    if (n >= NCv) return;
    int s = 0;
    #pragma unroll
    for (int l = 0; l < LTv; l++) s += g_hist[l * NBv + g_coden[l * NCv + n]];
    g_score[n] = s;
}

// ---------------- stable top-S selection ----------------
__global__ void select_kernel()
{
    __shared__ int ssc[NCv];
    __shared__ int red[1024];
    int tid = threadIdx.x;
    for (int i = tid; i < NCv; i += 1024) ssc[i] = g_score[i];
    __syncthreads();

    int lo = 0, hi = LTv * TPPv + 1;
    while (lo + 1 < hi) {
        int mid = (lo + hi) >> 1;
        int c = 0;
        for (int i = tid; i < NCv; i += 1024) c += (ssc[i] >= mid);
        red[tid] = c; __syncthreads();
        for (int st = 512; st > 0; st >>= 1) { if (tid < st) red[tid] += red[tid + st]; __syncthreads(); }
        int tot = red[0]; __syncthreads();
        if (tot >= SSv) lo = mid; else hi = mid;
    }
    int tau = lo;
    int c = 0;
    for (int i = tid; i < NCv; i += 1024) c += (ssc[i] > tau);
    red[tid] = c; __syncthreads();
    for (int st = 512; st > 0; st >>= 1) { if (tid < st) red[tid] += red[tid + st]; __syncthreads(); }
    int m = red[0];
    int need = SSv - m;
    __syncthreads();

    int base = tid * 4;
    int gtp[4], eqp[4];
    int lgt = 0, leq = 0;
    #pragma unroll
    for (int j = 0; j < 4; j++) {
        int sc = ssc[base + j];
        gtp[j] = lgt; eqp[j] = leq;
        lgt += (sc > tau); leq += (sc == tau);
    }
    red[tid] = (lgt << 16) | leq; __syncthreads();
    for (int off = 1; off < 1024; off <<= 1) {
        int vv = (tid >= off) ? red[tid - off] : 0;
        __syncthreads();
        red[tid] += vv;
        __syncthreads();
    }
    int excl = (tid == 0) ? 0 : red[tid - 1];
    int egt = excl >> 16, eeq = excl & 0xffff;
    #pragma unroll
    for (int j = 0; j < 4; j++) {
        int sc = ssc[base + j];
        if (sc > tau)                                g_sids[egt + gtp[j]] = base + j;
        else if (sc == tau && (eeq + eqp[j]) < need) g_sids[m + eeq + eqp[j]] = base + j;
    }
}

// ---------------- gathers ----------------
__global__ void gather_kernel(const float* __restrict__ W1, const float* __restrict__ b1)
{
    int idx = blockIdx.x * 256 + threadIdx.x;
    if (idx >= SSv * Dv) return;
    int s = idx >> 10, dcol = idx & 1023;
    int row = g_sids[s];
    g_w1s[idx] = W1[(size_t)row * Dv + dcol];
    if (dcol == 0) g_b1s[s] = b1[row];
}
__global__ void gatherT_kernel(const float* __restrict__ W2)
{
    __shared__ float tile[32][33];
    int s0 = blockIdx.x * 32, d0 = blockIdx.y * 32;
    int tx = threadIdx.x & 31, ty8 = threadIdx.x >> 5;
    for (int r = ty8; r < 32; r += 8) {
        int row = g_sids[s0 + r];
        tile[r][tx] = W2[(size_t)row * Dv + d0 + tx];
    }
    __syncthreads();
    for (int r = ty8; r < 32; r += 8)
        g_w2sT[(size_t)(d0 + r) * SSv + s0 + tx] = tile[tx][r];
}
__global__ void tanhpns_kernel()
{
    int idx = blockIdx.x * 256 + threadIdx.x;
    if (idx >= SSv * LKv) return;
    int s = idx >> 7, lk = idx & 127;
    g_tanhpns[idx] = tanhf(g_projn[(size_t)lk * NCv + g_sids[s]]);
}

// ---------------- triplet loss (warp per token, shuffle-only) ----------------
__global__ void __launch_bounds__(256)
triplet2(int chunk)
{
    __shared__ float vals[8][1024];
    int w = threadIdx.x >> 5, lane = threadIdx.x & 31;
    int t = blockIdx.x * 8 + w;
    const float* lrow = g_logits + (size_t)t * SSv;

    float apos = 0.f, aneg = 0.f;
    for (int phase = 0; phase < 2; phase++) {
        for (int i = lane; i < 256; i += 32)
            ((float4*)vals[w])[i] = ((const float4*)lrow)[i];
        __syncwarp();
        float sv[4] = {0.f, 0.f, 0.f, 0.f};
        for (int it = 0; it < PPv; it++) {
            float bv = (phase == 0) ? -1e30f : 1e30f;
            int bi = 1 << 30;
            #pragma unroll
            for (int qd = 0; qd < 32; qd++) {
                int i = lane + (qd << 5);
                float x = vals[w][i];
                bool better = (phase == 0) ? (x > bv) : (x < bv);
                if (better) { bv = x; bi = i; }
            }
            #pragma unroll
            for (int off = 16; off > 0; off >>= 1) {
                float ov = __shfl_xor_sync(0xffffffffu, bv, off);
                int   oi = __shfl_xor_sync(0xffffffffu, bi, off);
                bool take = (phase == 0)
                    ? (ov > bv || (ov == bv && oi < bi))
                    : (ov < bv || (ov == bv && oi < bi));
                if (take) { bv = ov; bi = oi; }
            }
            #pragma unroll
            for (int c2 = 0; c2 < 4; c2++)
                sv[c2] += g_tanhpns[(size_t)bi * LKv + lane + 32 * c2];
            if (lane == 0) vals[w][bi] = (phase == 0) ? -1e30f : 1e30f;
            __syncwarp();
        }
        float a = 0.f;
        #pragma unroll
        for (int c2 = 0; c2 < 4; c2++)
            a += sv[c2] * g_tanhpt[(size_t)t * LKv + lane + 32 * c2];
        #pragma unroll
        for (int off = 16; off > 0; off >>= 1)
            a += __shfl_xor_sync(0xffffffffu, a, off);
        a *= 1.0f / (128.0f * 64.0f);
        if (phase == 0) apos = a; else aneg = a;
    }
    if (lane == 0) g_trip[chunk * TPPv + t] = fmaxf(aneg - apos + 0.5f, 0.f);
}

__global__ void trip_reduce(float* __restrict__ outp)
{
    __shared__ float red[1024];
    int tid = threadIdx.x;
    red[tid] = g_trip[tid] + g_trip[tid + 1024];
    __syncthreads();
    for (int st = 512; st > 0; st >>= 1) { if (tid < st) red[tid] += red[tid + st]; __syncthreads(); }
    if (tid == 0) *outp = red[0] * (1.0f / 2048.0f);
}

// ---------------- host ----------------
extern "C" void kernel_launch(void* const* d_in, const int* in_sizes, int n_in,
                              void* d_out, int out_size)
{
    const float* hidden = (const float*)d_in[0];
    const float* amask  = (const float*)d_in[1];
    const float* ln1_g  = (const float*)d_in[2];
    const float* ln1_b  = (const float*)d_in[3];
    const float* Wq     = (const float*)d_in[4];
    const float* bq     = (const float*)d_in[5];
    const float* Wk     = (const float*)d_in[6];
    const float* bk     = (const float*)d_in[7];
    const float* Wv     = (const float*)d_in[8];
    const float* bv     = (const float*)d_in[9];
    const float* Wo     = (const float*)d_in[10];
    const float* bo     = (const float*)d_in[11];
    const float* ln2_g  = (const float*)d_in[12];
    const float* ln2_b  = (const float*)d_in[13];
    const float* W1     = (const float*)d_in[14];
    const float* b1     = (const float*)d_in[15];
    const float* Whash  = (const float*)d_in[16];
    const float* W2     = (const float*)d_in[17];
    const float* b2     = (const float*)d_in[18];
    float* out = (float*)d_out;

    float *xln, *q, *k, *v, *ctx, *attn, *normed, *projn, *projt;
    float *w1s, *w2sT, *b1s, *logits, *acts;
    cudaGetSymbolAddress((void**)&xln,    g_xln);
    cudaGetSymbolAddress((void**)&q,      g_q);
    cudaGetSymbolAddress((void**)&k,      g_k);
    cudaGetSymbolAddress((void**)&v,      g_v);
    cudaGetSymbolAddress((void**)&ctx,    g_ctx);
    cudaGetSymbolAddress((void**)&attn,   g_attn);
    cudaGetSymbolAddress((void**)&normed, g_normed);
    cudaGetSymbolAddress((void**)&projn,  g_projn);
    cudaGetSymbolAddress((void**)&projt,  g_projt);
    cudaGetSymbolAddress((void**)&w1s,    g_w1s);
    cudaGetSymbolAddress((void**)&w2sT,   g_w2sT);
    cudaGetSymbolAddress((void**)&b1s,    g_b1s);
    cudaGetSymbolAddress((void**)&logits, g_logits);
    cudaGetSymbolAddress((void**)&acts,   g_acts);

    // dynamic smem opt-in
    const int SM3  = (128 + 128) * 36 * 4 * 2;   // 73728
    const int SM1  = (64 + 128) * 36 * 4;        // 27648
    const int SMAT = (4 * 64 * 65 + 64) * 4;     // 66816
    cudaFuncSetAttribute((const void*)mma_nt<3,0,true,false,128,128>,
                         cudaFuncAttributeMaxDynamicSharedMemorySize, SM3);
    cudaFuncSetAttribute((const void*)mma_nt<3,0,true,true,128,128>,
                         cudaFuncAttributeMaxDynamicSharedMemorySize, SM3);
    cudaFuncSetAttribute((const void*)mma_nt<1,1,true,false,64,128>,
                         cudaFuncAttributeMaxDynamicSharedMemorySize, SM1);
    cudaFuncSetAttribute((const void*)mma_nt<1,0,true,true,64,128>,
                         cudaFuncAttributeMaxDynamicSharedMemorySize, SM1);
    cudaFuncSetAttribute((const void*)attn2,
                         cudaFuncAttributeMaxDynamicSharedMemorySize, SMAT);

    // ---- attention path ----
    ln_kernel<<<SQv, 256>>>(hidden, ln1_g, ln1_b, xln);
    dim3 gA(Dv/128, SQv/128);   // (8,16)
    mma_nt<3,0,true,false,128,128><<<gA, 256, SM3>>>(xln, Wq, bq, nullptr, q,   nullptr, SQv, Dv, Dv);
    mma_nt<3,0,true,false,128,128><<<gA, 256, SM3>>>(xln, Wk, bk, nullptr, k,   nullptr, SQv, Dv, Dv);
    mma_nt<3,0,true,false,128,128><<<gA, 256, SM3>>>(xln, Wv, bv, nullptr, v,   nullptr, SQv, Dv, Dv);
    attn2<<<dim3(SQv/64, Hv), 256, SMAT>>>(q, k, v, amask, ctx);
    mma_nt<3,0,true,true,128,128><<<gA, 256, SM3>>>(ctx, Wo, bo, hidden, attn, nullptr, SQv, Dv, Dv);

    // ---- FFN prep ----
    ln_kernel<<<SQv, 256>>>(attn, ln2_g, ln2_b, normed);
    gemm_nt<false><<<dim3(NCv/64, LKv/64), 256>>>(Whash, W1, nullptr, projn, LKv, NCv, Dv);
    coden_kernel<<<(LTv * NCv) / 256, 256>>>();

    // ---- per-chunk LSH FFN ----
    dim3 gB(SSv/128, TPPv/64); // (8,16)
    for (int c = 0; c < 2; c++) {
        const float* hch = normed + (size_t)c * TPPv * Dv;
        const float* ach = attn   + (size_t)c * TPPv * Dv;
        float*       och = out    + (size_t)c * TPPv * Dv;

        gemm_nt<false><<<dim3(TPPv/64, LKv/64), 256>>>(Whash, hch, nullptr, projt, LKv, TPPv, Dv);
        codet_kernel<<<(LTv * TPPv) / 256, 256>>>();
        tanhpt_kernel<<<(TPPv * LKv) / 256, 256>>>();
        hist_zero<<<(LTv * NBv) / 256, 256>>>();
        hist_build<<<(LTv * TPPv) / 256, 256>>>();
        score_kernel<<<NCv / 256, 256>>>();
        select_kernel<<<1, 1024>>>();
        gather_kernel<<<(SSv * Dv) / 256, 256>>>(W1, b1);
        gatherT_kernel<<<dim3(SSv/32, Dv/32), 256>>>(W2);
        tanhpns_kernel<<<(SSv * LKv) / 256, 256>>>();

        // logits (+ fused GELU into acts)
        mma_nt<1,1,true,false,64,128><<<gB, 256, SM1>>>(hch, w1s, b1s, nullptr,
                                                        logits, acts, TPPv, SSv, Dv);
        triplet2<<<TPPv/8, 256>>>(c);
        // out = acts @ W2s + b2 + attn_residual
        mma_nt<1,0,true,true,64,128><<<dim3(Dv/128, TPPv/64), 256, SM1>>>(acts, w2sT, b2, ach,
                                                                          och, nullptr, TPPv, Dv, SSv);
    }

    // ---- scalar output ----
    trip_reduce<<<1, 1024>>>(out + (size_t)SQv * Dv);
}